// round 3
// baseline (speedup 1.0000x reference)
#include <cuda_runtime.h>
#include <cstdint>

#define HH 1024
#define WW 1024
#define CF 8
#define HWs (HH*WW)
#define BIGV 1e18f
#define L2E 1.4426950408889634f

typedef unsigned long long ull;

__device__ __forceinline__ ull pk(float a, float b) {
    ull r;
    asm("mov.b64 %0, {%1, %2};" : "=l"(r) : "f"(a), "f"(b));
    return r;
}
__device__ __forceinline__ void upk(ull v, float& a, float& b) {
    asm("mov.b64 {%0, %1}, %2;" : "=f"(a), "=f"(b) : "l"(v));
}
__device__ __forceinline__ ull fma2(ull a, ull b, ull c) {
    ull d;
    asm("fma.rn.f32x2 %0, %1, %2, %3;" : "=l"(d) : "l"(a), "l"(b), "l"(c));
    return d;
}
__device__ __forceinline__ ull add2(ull a, ull b) {
    ull d;
    asm("add.rn.f32x2 %0, %1, %2;" : "=l"(d) : "l"(a), "l"(b));
    return d;
}
__device__ __forceinline__ float ex2(float x) {
    float y;
    asm("ex2.approx.f32 %0, %1;" : "=f"(y) : "f"(x));
    return y;
}

// Tile: 64 wide x 8 high. Threads (32,8); thread tx handles pixels X0+tx and X0+tx+32.
// SMEM holds PAIR-INTERLEAVED data: ps[c][r][q] = {f[X0-3+q], f[X0+29+q]} as a packed
// 8-byte pair. Tap (dy,dx,c) for thread tx is ONE aligned LDS.64 at q = tx+dx
// (lanes contiguous over 256B -> conflict-free), and the loaded 64-bit value IS the
// packed fn pair — no per-tap register-combine MOVs.
// q needed: tx+dx in [0, 37]; allocate 40 per row.
#define QW 40

__global__ __launch_bounds__(256, 2)
void bilateral_kernel(const float* __restrict__ in, float* __restrict__ out)
{
    __shared__ ull ps[CF][14][QW];
    const int tx = threadIdx.x, ty = threadIdx.y;
    const int X0 = blockIdx.x * 64;
    const int Y0 = blockIdx.y * 8;
    const int b  = blockIdx.z;
    const float* __restrict__ inb = in + (size_t)b * 18 * HWs;

    // ---- fill pair-interleaved SMEM (+halo), sentinel for OOB ----
    const int tid = ty * 32 + tx;
    for (int i = tid; i < CF * 14 * QW; i += 256) {
        int c   = i / (14 * QW);
        int rem = i - c * (14 * QW);
        int r   = rem / QW;
        int q   = rem - r * QW;
        int gy  = Y0 - 3 + r;
        int gxa = X0 - 3 + q;
        int gxb = X0 + 29 + q;
        float va = BIGV, vb = BIGV;
        if ((unsigned)gy < HH) {
            const float* rowg = inb + c * HWs + gy * WW;
            if ((unsigned)gxa < WW) va = rowg[gxa];
            if ((unsigned)gxb < WW) vb = rowg[gxb];
        }
        ps[c][r][q] = pk(va, vb);
    }
    __syncthreads();

    const int gx0 = X0 + tx, gx1 = gx0 + 32;
    const int gy  = Y0 + ty;

    // ---- per-pixel precompute: rp' = -(p^2)*log2(e), u = -2 rp' f, v = sum rp' f^2 ----
    ull rpp[CF], up[CF];
    float v0 = 0.f, v1 = 0.f;
    const float* __restrict__ pb = inb + 8 * HWs + gy * WW;
    #pragma unroll
    for (int c = 0; c < CF; c++) {
        float p0 = pb[c * HWs + gx0];
        float p1 = pb[c * HWs + gx1];
        float r0 = -(p0 * p0) * L2E;
        float r1 = -(p1 * p1) * L2E;
        float f0, f1;
        upk(ps[c][ty + 3][tx + 3], f0, f1);   // center pair
        v0 = fmaf(r0 * f0, f0, v0);
        v1 = fmaf(r1 * f1, f1, v1);
        rpp[c] = pk(r0, r1);
        up[c]  = pk(-2.f * r0 * f0, -2.f * r1 * f1);
    }
    float sxa = pb[8 * HWs + gx0], sxb = pb[8 * HWs + gx1];
    float sya = pb[9 * HWs + gx0], syb = pb[9 * HWs + gx1];
    const ull sxp = pk(-(sxa * sxa) * L2E, -(sxb * sxb) * L2E);
    const ull syp = pk(-(sya * sya) * L2E, -(syb * syb) * L2E);
    const ull vp  = pk(v0, v1);

    const ull d1 = pk(1.f, 1.f);
    const ull d4 = pk(4.f, 4.f);
    const ull d9 = pk(9.f, 9.f);

    ull acc0 = 0ULL, acc1 = 0ULL, acc2 = 0ULL, wsp = 0ULL;

    for (int dy = 0; dy < 7; dy++) {
        float dyf = (float)((dy - 3) * (dy - 3));
        ull rb = fma2(syp, pk(dyf, dyf), vp);
        const ull* __restrict__ rowp = &ps[0][ty + dy][tx];
        #pragma unroll
        for (int dx = 0; dx < 7; dx++) {
            ull lw;
            if      (dx == 3)             lw = rb;
            else if (dx == 2 || dx == 4)  lw = fma2(sxp, d1, rb);
            else if (dx == 1 || dx == 5)  lw = fma2(sxp, d4, rb);
            else                          lw = fma2(sxp, d9, rb);

            ull fn0 = 0, fn1 = 0, fn2 = 0;
            #pragma unroll
            for (int c = 0; c < CF; c++) {
                ull fnp = rowp[c * (14 * QW) + dx];      // one LDS.64 = packed pair
                ull s   = fma2(rpp[c], fnp, up[c]);
                lw = fma2(s, fnp, lw);
                if (c == 0) fn0 = fnp;
                else if (c == 1) fn1 = fnp;
                else if (c == 2) fn2 = fnp;
            }
            float l0, l1;
            upk(lw, l0, l1);
            ull wp2 = pk(ex2(l0), ex2(l1));
            acc0 = fma2(wp2, fn0, acc0);
            acc1 = fma2(wp2, fn1, acc1);
            acc2 = fma2(wp2, fn2, acc2);
            wsp  = add2(wsp, wp2);
        }
    }

    float ws0, ws1, a0, a1;
    upk(wsp, ws0, ws1);
    float* __restrict__ ob = out + (size_t)b * 3 * HWs + gy * WW;
    upk(acc0, a0, a1); ob[gx0]           = a0 / ws0; ob[gx1]           = a1 / ws1;
    upk(acc1, a0, a1); ob[HWs + gx0]     = a0 / ws0; ob[HWs + gx1]     = a1 / ws1;
    upk(acc2, a0, a1); ob[2 * HWs + gx0] = a0 / ws0; ob[2 * HWs + gx1] = a1 / ws1;
}

extern "C" void kernel_launch(void* const* d_in, const int* in_sizes, int n_in,
                              void* d_out, int out_size) {
    const float* in = (const float*)d_in[0];
    float* out = (float*)d_out;
    dim3 grid(WW / 64, HH / 8, 2);
    dim3 block(32, 8);
    bilateral_kernel<<<grid, block>>>(in, out);
}

// round 4
// speedup vs baseline: 1.3331x; 1.3331x over previous
#include <cuda_runtime.h>
#include <cstdint>

#define HH 1024
#define WW 1024
#define CF 8
#define HWs (HH*WW)
#define BIGV 1e9f
#define L2E 1.4426950408889634f

typedef unsigned long long ull;

__device__ __forceinline__ ull pk(float a, float b) {
    ull r;
    asm("mov.b64 %0, {%1, %2};" : "=l"(r) : "f"(a), "f"(b));
    return r;
}
__device__ __forceinline__ void upk(ull v, float& a, float& b) {
    asm("mov.b64 {%0, %1}, %2;" : "=f"(a), "=f"(b) : "l"(v));
}
__device__ __forceinline__ ull fma2(ull a, ull b, ull c) {
    ull d;
    asm("fma.rn.f32x2 %0, %1, %2, %3;" : "=l"(d) : "l"(a), "l"(b), "l"(c));
    return d;
}
__device__ __forceinline__ ull add2(ull a, ull b) {
    ull d;
    asm("add.rn.f32x2 %0, %1, %2;" : "=l"(d) : "l"(a), "l"(b));
    return d;
}
__device__ __forceinline__ float ex2(float x) {
    float y;
    asm("ex2.approx.f32 %0, %1;" : "=f"(y) : "f"(x));
    return y;
}
__device__ __forceinline__ float frcp(float x) {
    float y;
    asm("rcp.approx.f32 %0, %1;" : "=f"(y) : "f"(x));
    return y;
}

// Tile: 64 wide x 8 high. Threads (32,8); thread tx handles pixels X0+tx and X0+tx+32
// (stride-32 pairing -> lane-consecutive LDS.32, conflict-free).
// SMEM: 8 channels x 14 rows x 72 cols of float (R2 scheme: LDS.32 + pk beats LDS.64,
// measured R3).
__global__ __launch_bounds__(256, 3)
void bilateral_kernel(const float* __restrict__ in, float* __restrict__ out)
{
    __shared__ float smf[CF][14][72];
    const int tx = threadIdx.x, ty = threadIdx.y;
    const int X0 = blockIdx.x * 64;
    const int Y0 = blockIdx.y * 8;
    const int b  = blockIdx.z;
    const float* __restrict__ inb = in + (size_t)b * 18 * HWs;

    // ---- load filterable channels (+halo) into SMEM, sentinel for OOB ----
    const int tid = ty * 32 + tx;
    for (int i = tid; i < CF * 14 * 72; i += 256) {
        int c   = i / (14 * 72);
        int rem = i - c * (14 * 72);
        int r   = rem / 72;
        int col = rem - r * 72;
        int gy = Y0 - 3 + r;
        int gx = X0 - 3 + col;
        float v = BIGV;
        if ((unsigned)gx < WW && (unsigned)gy < HH)
            v = inb[c * HWs + gy * WW + gx];
        smf[c][r][col] = v;
    }
    __syncthreads();

    const int gx0 = X0 + tx, gx1 = gx0 + 32;
    const int gy  = Y0 + ty;

    // ---- per-pixel precompute: rp' = -(p^2)*log2(e), u = -2 rp' f, v = sum rp' f^2 ----
    ull rpp[CF], up[CF];
    float v0 = 0.f, v1 = 0.f;
    const float* __restrict__ pb = inb + 8 * HWs + gy * WW;
    #pragma unroll
    for (int c = 0; c < CF; c++) {
        float p0 = pb[c * HWs + gx0];
        float p1 = pb[c * HWs + gx1];
        float r0 = -(p0 * p0) * L2E;
        float r1 = -(p1 * p1) * L2E;
        float f0 = smf[c][ty + 3][tx + 3];
        float f1 = smf[c][ty + 3][tx + 35];
        v0 = fmaf(r0 * f0, f0, v0);
        v1 = fmaf(r1 * f1, f1, v1);
        rpp[c] = pk(r0, r1);
        up[c]  = pk(-2.f * r0 * f0, -2.f * r1 * f1);
    }
    float sxa = pb[8 * HWs + gx0], sxb = pb[8 * HWs + gx1];
    float sya = pb[9 * HWs + gx0], syb = pb[9 * HWs + gx1];
    const ull sxp = pk(-(sxa * sxa) * L2E, -(sxb * sxb) * L2E);
    const ull syp = pk(-(sya * sya) * L2E, -(syb * syb) * L2E);
    const ull vp  = pk(v0, v1);

    ull acc0 = 0ULL, acc1 = 0ULL, acc2 = 0ULL, wsp = 0ULL;
    const ull zz = 0ULL;

    for (int dy = 0; dy < 7; dy++) {
        float dyf = (float)((dy - 3) * (dy - 3));
        // 4 distinct lw bases per row: rb + {0,1,4,9}*sxp
        ull lwb0 = fma2(syp, pk(dyf, dyf), vp);
        ull lwb1 = fma2(sxp, pk(1.f, 1.f), lwb0);
        ull lwb2 = fma2(sxp, pk(4.f, 4.f), lwb0);
        ull lwb3 = fma2(sxp, pk(9.f, 9.f), lwb0);
        const float* __restrict__ rowp = &smf[0][ty + dy][tx];
        #pragma unroll
        for (int dx = 0; dx < 7; dx++) {
            ull base;
            if      (dx == 3)             base = lwb0;
            else if (dx == 2 || dx == 4)  base = lwb1;
            else if (dx == 1 || dx == 5)  base = lwb2;
            else                          base = lwb3;

            // two 4-deep chains instead of one 8-deep
            ull fn0 = 0, fn1 = 0, fn2 = 0;
            ull lwA = base, lwB = zz;
            #pragma unroll
            for (int c = 0; c < CF; c++) {
                const float* p = rowp + c * (14 * 72) + dx;
                ull fnp = pk(p[0], p[32]);
                ull s   = fma2(rpp[c], fnp, up[c]);
                if (c < 4) lwA = fma2(s, fnp, lwA);
                else       lwB = fma2(s, fnp, lwB);
                if (c == 0) fn0 = fnp;
                else if (c == 1) fn1 = fnp;
                else if (c == 2) fn2 = fnp;
            }
            ull lw = add2(lwA, lwB);
            float l0, l1;
            upk(lw, l0, l1);
            ull wp2 = pk(ex2(l0), ex2(l1));
            acc0 = fma2(wp2, fn0, acc0);
            acc1 = fma2(wp2, fn1, acc1);
            acc2 = fma2(wp2, fn2, acc2);
            wsp  = add2(wsp, wp2);
        }
    }

    float ws0, ws1, a0, a1;
    upk(wsp, ws0, ws1);
    const float i0 = frcp(ws0), i1 = frcp(ws1);
    float* __restrict__ ob = out + (size_t)b * 3 * HWs + gy * WW;
    upk(acc0, a0, a1); ob[gx0]           = a0 * i0; ob[gx1]           = a1 * i1;
    upk(acc1, a0, a1); ob[HWs + gx0]     = a0 * i0; ob[HWs + gx1]     = a1 * i1;
    upk(acc2, a0, a1); ob[2 * HWs + gx0] = a0 * i0; ob[2 * HWs + gx1] = a1 * i1;
}

extern "C" void kernel_launch(void* const* d_in, const int* in_sizes, int n_in,
                              void* d_out, int out_size) {
    const float* in = (const float*)d_in[0];
    float* out = (float*)d_out;
    dim3 grid(WW / 64, HH / 8, 2);
    dim3 block(32, 8);
    bilateral_kernel<<<grid, block>>>(in, out);
}

// round 5
// speedup vs baseline: 1.6586x; 1.2441x over previous
#include <cuda_runtime.h>
#include <cstdint>

#define HH 1024
#define WW 1024
#define HWs (HH*WW)
#define BIGV 1e9f
#define NEGB (-1e9f)
#define L2E 1.4426950408889634f

#define XW 71          // x window: [X0-3, X0+67]
#define PSTR 10        // floats per pixel slot (8 ch + 2 pad -> 40B, 8B aligned, 2-phase banks)
#define RSTR (XW*PSTR) // floats per row

typedef unsigned long long ull;

__device__ __forceinline__ ull pk(float a, float b) {
    ull r;
    asm("mov.b64 %0, {%1, %2};" : "=l"(r) : "f"(a), "f"(b));
    return r;
}
__device__ __forceinline__ void upk(ull v, float& a, float& b) {
    asm("mov.b64 {%0, %1}, %2;" : "=f"(a), "=f"(b) : "l"(v));
}
__device__ __forceinline__ ull fma2(ull a, ull b, ull c) {
    ull d;
    asm("fma.rn.f32x2 %0, %1, %2, %3;" : "=l"(d) : "l"(a), "l"(b), "l"(c));
    return d;
}
__device__ __forceinline__ float ex2(float x) {
    float y;
    asm("ex2.approx.f32 %0, %1;" : "=f"(y) : "f"(x));
    return y;
}
__device__ __forceinline__ float frcp(float x) {
    float y;
    asm("rcp.approx.f32 %0, %1;" : "=f"(y) : "f"(x));
    return y;
}

// Tile 64 wide x 8 tall. Block (64,4); thread (tx,ty) owns pixels
// (X0+tx, Y0+2ty) and (X0+tx, Y0+2ty+1) — vertically adjacent, so each
// loaded neighbor row value serves BOTH pixels (1.75x fewer shared loads).
// SMEM is channel-interleaved: smf[14 rows][71 x][10 floats]; a single
// LDS.64 yields channel pair {c,c+1} used directly by both pixel chains.
__global__ __launch_bounds__(256, 3)
void bilateral_kernel(const float* __restrict__ in, float* __restrict__ out)
{
    __shared__ float smf[14 * RSTR];   // 39760 B
    const int tx = threadIdx.x, ty = threadIdx.y;
    const int X0 = blockIdx.x * 64;
    const int Y0 = blockIdx.y * 8;
    const int b  = blockIdx.z;
    const float* __restrict__ inb = in + (size_t)b * 18 * HWs;

    // ---- fill channel-interleaved SMEM (+halo), sentinel for OOB ----
    const int tid = ty * 64 + tx;
    for (int i = tid; i < 14 * XW; i += 256) {
        int r = i / XW;
        int x = i - r * XW;
        int gy = Y0 - 3 + r;
        int gx = X0 - 3 + x;
        bool ok = ((unsigned)gx < WW) & ((unsigned)gy < HH);
        const float* g = inb + (size_t)gy * WW + gx;
        float v0 = ok ? g[0 * HWs] : BIGV;
        float v1 = ok ? g[1 * HWs] : BIGV;
        float v2 = ok ? g[2 * HWs] : BIGV;
        float v3 = ok ? g[3 * HWs] : BIGV;
        float v4 = ok ? g[4 * HWs] : BIGV;
        float v5 = ok ? g[5 * HWs] : BIGV;
        float v6 = ok ? g[6 * HWs] : BIGV;
        float v7 = ok ? g[7 * HWs] : BIGV;
        ull* d = (ull*)&smf[r * RSTR + x * PSTR];
        d[0] = pk(v0, v1); d[1] = pk(v2, v3);
        d[2] = pk(v4, v5); d[3] = pk(v6, v7);
    }
    __syncthreads();

    const int gx = X0 + tx;
    const int ya = Y0 + 2 * ty;      // pixel a
    // pixel b = ya + 1

    // ---- per-pixel precompute (channel-packed): rp' = -(p^2)*log2(e),
    //      u = -2 rp' f, v = sum rp' f^2 ----
    ull rppA[4], rppB[4], upA[4], upB[4];
    float va = 0.f, vb = 0.f;
    const float* __restrict__ pa = inb + 8 * HWs + (size_t)ya * WW + gx;
    const float* __restrict__ pbp = pa + WW;
    const float* __restrict__ ca = &smf[(2 * ty + 3) * RSTR + (tx + 3) * PSTR];
    const float* __restrict__ cb = ca + RSTR;
    #pragma unroll
    for (int k = 0; k < 4; k++) {
        float p0a = pa[(2*k) * HWs],  p1a = pa[(2*k+1) * HWs];
        float p0b = pbp[(2*k) * HWs], p1b = pbp[(2*k+1) * HWs];
        float r0a = -(p0a * p0a) * L2E, r1a = -(p1a * p1a) * L2E;
        float r0b = -(p0b * p0b) * L2E, r1b = -(p1b * p1b) * L2E;
        float f0a = ca[2*k], f1a = ca[2*k+1];
        float f0b = cb[2*k], f1b = cb[2*k+1];
        va = fmaf(r0a * f0a, f0a, va); va = fmaf(r1a * f1a, f1a, va);
        vb = fmaf(r0b * f0b, f0b, vb); vb = fmaf(r1b * f1b, f1b, vb);
        rppA[k] = pk(r0a, r1a);
        rppB[k] = pk(r0b, r1b);
        upA[k]  = pk(-2.f * r0a * f0a, -2.f * r1a * f1a);
        upB[k]  = pk(-2.f * r0b * f0b, -2.f * r1b * f1b);
    }
    float qa, qb;
    qa = pa[8 * HWs];  qb = pbp[8 * HWs];
    const float sxa = -(qa * qa) * L2E, sxb = -(qb * qb) * L2E;
    qa = pa[9 * HWs];  qb = pbp[9 * HWs];
    const float sya = -(qa * qa) * L2E, syb = -(qb * qb) * L2E;

    float acc0a = 0.f, acc1a = 0.f, acc2a = 0.f, wsa = 0.f;
    float acc0b = 0.f, acc1b = 0.f, acc2b = 0.f, wsb = 0.f;

    // ---- main loop over 8 absolute rows (rolled), dx & channels unrolled ----
    for (int rr = 0; rr < 8; rr++) {
        int r = 2 * ty + rr;
        float da = (float)(rr - 3), db = (float)(rr - 4);
        float rba = (rr <= 6) ? fmaf(sya, da * da, va) : NEGB;  // mask invalid row for px a
        float rbb = (rr >= 1) ? fmaf(syb, db * db, vb) : NEGB;  // mask invalid row for px b
        const float* __restrict__ rowp = &smf[r * RSTR + tx * PSTR];
        #pragma unroll
        for (int dx = 0; dx < 7; dx++) {
            const float ddv = (float)((dx - 3) * (dx - 3));
            float ba = (dx == 3) ? rba : fmaf(sxa, ddv, rba);
            float bb = (dx == 3) ? rbb : fmaf(sxb, ddv, rbb);

            const ull* __restrict__ p = (const ull*)(rowp + dx * PSTR);
            ull f01 = p[0], f23 = p[1], f45 = p[2], f67 = p[3];

            ull lwa = pk(ba, 0.f);
            ull lwb = pk(bb, 0.f);
            {
                ull s;
                s = fma2(rppA[0], f01, upA[0]); lwa = fma2(s, f01, lwa);
                s = fma2(rppB[0], f01, upB[0]); lwb = fma2(s, f01, lwb);
                s = fma2(rppA[1], f23, upA[1]); lwa = fma2(s, f23, lwa);
                s = fma2(rppB[1], f23, upB[1]); lwb = fma2(s, f23, lwb);
                s = fma2(rppA[2], f45, upA[2]); lwa = fma2(s, f45, lwa);
                s = fma2(rppB[2], f45, upB[2]); lwb = fma2(s, f45, lwb);
                s = fma2(rppA[3], f67, upA[3]); lwa = fma2(s, f67, lwa);
                s = fma2(rppB[3], f67, upB[3]); lwb = fma2(s, f67, lwb);
            }
            float ea, oa, eb, ob2;
            upk(lwa, ea, oa);
            upk(lwb, eb, ob2);
            float wa = ex2(ea + oa);
            float wb = ex2(eb + ob2);

            float f0, f1, f2, f3u;
            upk(f01, f0, f1);
            upk(f23, f2, f3u);
            acc0a = fmaf(wa, f0, acc0a);
            acc1a = fmaf(wa, f1, acc1a);
            acc2a = fmaf(wa, f2, acc2a);
            wsa += wa;
            acc0b = fmaf(wb, f0, acc0b);
            acc1b = fmaf(wb, f1, acc1b);
            acc2b = fmaf(wb, f2, acc2b);
            wsb += wb;
        }
    }

    const float ia = frcp(wsa), ib = frcp(wsb);
    float* __restrict__ oa = out + (size_t)b * 3 * HWs + (size_t)ya * WW + gx;
    float* __restrict__ ob = oa + WW;
    oa[0]       = acc0a * ia;  ob[0]       = acc0b * ib;
    oa[HWs]     = acc1a * ia;  ob[HWs]     = acc1b * ib;
    oa[2 * HWs] = acc2a * ia;  ob[2 * HWs] = acc2b * ib;
}

extern "C" void kernel_launch(void* const* d_in, const int* in_sizes, int n_in,
                              void* d_out, int out_size) {
    const float* in = (const float*)d_in[0];
    float* out = (float*)d_out;
    dim3 grid(WW / 64, HH / 8, 2);
    dim3 block(64, 4);
    bilateral_kernel<<<grid, block>>>(in, out);
}

// round 6
// speedup vs baseline: 1.7362x; 1.0468x over previous
#include <cuda_runtime.h>
#include <cstdint>

#define HH 1024
#define WW 1024
#define HWs (HH*WW)
#define BIGV 1e9f
#define NEGB (-1e9f)
#define L2E 1.4426950408889634f

#define XW 71          // x window: [X0-3, X0+67]
#define PSTR 12        // floats per pixel slot (8 ch + 4 pad -> 48B, 16B aligned for LDS.128)
#define RSTR (XW*PSTR) // floats per row

typedef unsigned long long ull;

__device__ __forceinline__ ull pk(float a, float b) {
    ull r;
    asm("mov.b64 %0, {%1, %2};" : "=l"(r) : "f"(a), "f"(b));
    return r;
}
__device__ __forceinline__ void upk(ull v, float& a, float& b) {
    asm("mov.b64 {%0, %1}, %2;" : "=f"(a), "=f"(b) : "l"(v));
}
__device__ __forceinline__ ull fma2(ull a, ull b, ull c) {
    ull d;
    asm("fma.rn.f32x2 %0, %1, %2, %3;" : "=l"(d) : "l"(a), "l"(b), "l"(c));
    return d;
}
__device__ __forceinline__ float ex2(float x) {
    float y;
    asm("ex2.approx.f32 %0, %1;" : "=f"(y) : "f"(x));
    return y;
}
__device__ __forceinline__ float frcp(float x) {
    float y;
    asm("rcp.approx.f32 %0, %1;" : "=f"(y) : "f"(x));
    return y;
}

// Tile 64 wide x 8 tall. Block (64,4); thread (tx,ty) owns pixels
// (X0+tx, Y0+2ty) and (X0+tx, Y0+2ty+1) — vertically adjacent; each loaded
// neighbor value serves BOTH pixels. SMEM is channel-interleaved with a 48B
// pixel slot so the 8 channels are fetched by TWO LDS.128 (conflict-free:
// stride-12 words covers all 32 banks once per 8-lane phase).
__global__ __launch_bounds__(256, 3)
void bilateral_kernel(const float* __restrict__ in, float* __restrict__ out)
{
    __shared__ float smf[14 * RSTR];   // 47712 B
    const int tx = threadIdx.x, ty = threadIdx.y;
    const int X0 = blockIdx.x * 64;
    const int Y0 = blockIdx.y * 8;
    const int b  = blockIdx.z;
    const float* __restrict__ inb = in + (size_t)b * 18 * HWs;

    // ---- fill channel-interleaved SMEM (+halo), sentinel for OOB ----
    const int tid = ty * 64 + tx;
    for (int i = tid; i < 14 * XW; i += 256) {
        int r = i / XW;
        int x = i - r * XW;
        int gy = Y0 - 3 + r;
        int gx = X0 - 3 + x;
        bool ok = ((unsigned)gx < WW) & ((unsigned)gy < HH);
        const float* g = inb + (size_t)gy * WW + gx;
        float4 u0, u1;
        u0.x = ok ? g[0 * HWs] : BIGV;
        u0.y = ok ? g[1 * HWs] : BIGV;
        u0.z = ok ? g[2 * HWs] : BIGV;
        u0.w = ok ? g[3 * HWs] : BIGV;
        u1.x = ok ? g[4 * HWs] : BIGV;
        u1.y = ok ? g[5 * HWs] : BIGV;
        u1.z = ok ? g[6 * HWs] : BIGV;
        u1.w = ok ? g[7 * HWs] : BIGV;
        float4* d = (float4*)&smf[r * RSTR + x * PSTR];
        d[0] = u0;
        d[1] = u1;
    }
    __syncthreads();

    const int gx = X0 + tx;
    const int ya = Y0 + 2 * ty;      // pixel a; pixel b = ya + 1

    // ---- per-pixel precompute: rp' = -(p^2)*log2(e), u = -2 rp' f, v = sum rp' f^2 ----
    ull rppA[4], rppB[4], upA[4], upB[4];
    float va = 0.f, vb = 0.f;
    const float* __restrict__ pa = inb + 8 * HWs + (size_t)ya * WW + gx;
    const float* __restrict__ pbp = pa + WW;
    const float* __restrict__ ca = &smf[(2 * ty + 3) * RSTR + (tx + 3) * PSTR];
    const float* __restrict__ cb = ca + RSTR;
    #pragma unroll
    for (int k = 0; k < 4; k++) {
        float p0a = pa[(2*k) * HWs],  p1a = pa[(2*k+1) * HWs];
        float p0b = pbp[(2*k) * HWs], p1b = pbp[(2*k+1) * HWs];
        float r0a = -(p0a * p0a) * L2E, r1a = -(p1a * p1a) * L2E;
        float r0b = -(p0b * p0b) * L2E, r1b = -(p1b * p1b) * L2E;
        float f0a = ca[2*k], f1a = ca[2*k+1];
        float f0b = cb[2*k], f1b = cb[2*k+1];
        va = fmaf(r0a * f0a, f0a, va); va = fmaf(r1a * f1a, f1a, va);
        vb = fmaf(r0b * f0b, f0b, vb); vb = fmaf(r1b * f1b, f1b, vb);
        rppA[k] = pk(r0a, r1a);
        rppB[k] = pk(r0b, r1b);
        upA[k]  = pk(-2.f * r0a * f0a, -2.f * r1a * f1a);
        upB[k]  = pk(-2.f * r0b * f0b, -2.f * r1b * f1b);
    }
    float qa, qb;
    qa = pa[8 * HWs];  qb = pbp[8 * HWs];
    const float sxa = -(qa * qa) * L2E, sxb = -(qb * qb) * L2E;
    qa = pa[9 * HWs];  qb = pbp[9 * HWs];
    const float sya = -(qa * qa) * L2E, syb = -(qb * qb) * L2E;

    ull acc01a = 0ULL, acc01b = 0ULL;
    float acc2a = 0.f, wsa = 0.f;
    float acc2b = 0.f, wsb = 0.f;

    // ---- main loop over 8 absolute rows (rolled), dx & channels unrolled ----
    for (int rr = 0; rr < 8; rr++) {
        int r = 2 * ty + rr;
        float da = (float)(rr - 3), db = (float)(rr - 4);
        float rba = (rr <= 6) ? fmaf(sya, da * da, va) : NEGB;  // mask invalid row for px a
        float rbb = (rr >= 1) ? fmaf(syb, db * db, vb) : NEGB;  // mask invalid row for px b
        const float* __restrict__ rowp = &smf[r * RSTR + tx * PSTR];
        #pragma unroll
        for (int dx = 0; dx < 7; dx++) {
            const float ddv = (float)((dx - 3) * (dx - 3));
            float ba = (dx == 3) ? rba : fmaf(sxa, ddv, rba);
            float bb = (dx == 3) ? rbb : fmaf(sxb, ddv, rbb);

            const ulonglong2* __restrict__ p = (const ulonglong2*)(rowp + dx * PSTR);
            ulonglong2 q0 = p[0];            // LDS.128: f01, f23
            ulonglong2 q1 = p[1];            // LDS.128: f45, f67
            ull f01 = q0.x, f23 = q0.y, f45 = q1.x, f67 = q1.y;

            ull lwa = pk(ba, 0.f);
            ull lwb = pk(bb, 0.f);
            {
                ull s;
                s = fma2(rppA[0], f01, upA[0]); lwa = fma2(s, f01, lwa);
                s = fma2(rppB[0], f01, upB[0]); lwb = fma2(s, f01, lwb);
                s = fma2(rppA[1], f23, upA[1]); lwa = fma2(s, f23, lwa);
                s = fma2(rppB[1], f23, upB[1]); lwb = fma2(s, f23, lwb);
                s = fma2(rppA[2], f45, upA[2]); lwa = fma2(s, f45, lwa);
                s = fma2(rppB[2], f45, upB[2]); lwb = fma2(s, f45, lwb);
                s = fma2(rppA[3], f67, upA[3]); lwa = fma2(s, f67, lwa);
                s = fma2(rppB[3], f67, upB[3]); lwb = fma2(s, f67, lwb);
            }
            float ea, oa, eb, ob2;
            upk(lwa, ea, oa);
            upk(lwb, eb, ob2);
            float wa = ex2(ea + oa);
            float wb = ex2(eb + ob2);

            // packed accumulate for channels 0,1; scalar for channel 2 + wsum
            acc01a = fma2(pk(wa, wa), f01, acc01a);
            acc01b = fma2(pk(wb, wb), f01, acc01b);
            float f2, f3u;
            upk(f23, f2, f3u);
            acc2a = fmaf(wa, f2, acc2a);  wsa += wa;
            acc2b = fmaf(wb, f2, acc2b);  wsb += wb;
        }
    }

    const float ia = frcp(wsa), ib = frcp(wsb);
    float a0, a1;
    float* __restrict__ oa = out + (size_t)b * 3 * HWs + (size_t)ya * WW + gx;
    float* __restrict__ ob = oa + WW;
    upk(acc01a, a0, a1);
    oa[0]   = a0 * ia;  oa[HWs] = a1 * ia;  oa[2 * HWs] = acc2a * ia;
    upk(acc01b, a0, a1);
    ob[0]   = a0 * ib;  ob[HWs] = a1 * ib;  ob[2 * HWs] = acc2b * ib;
}

extern "C" void kernel_launch(void* const* d_in, const int* in_sizes, int n_in,
                              void* d_out, int out_size) {
    const float* in = (const float*)d_in[0];
    float* out = (float*)d_out;
    dim3 grid(WW / 64, HH / 8, 2);
    dim3 block(64, 4);
    bilateral_kernel<<<grid, block>>>(in, out);
}